// round 13
// baseline (speedup 1.0000x reference)
#include <cuda_runtime.h>
#include <stdint.h>

// CutoutColor: out[n,c,h,w] = colors[n,c] if h in [top, top+28) && w in [left, left+28)
//              else x[n,c,h,w]
// x [4096, 9, 84, 84] f32, colors [4096, 9] f32, tops/lefts [4096] i32.
//
// R12: R11 structure (channel-fused float4, mask-once, front-batched loads,
// patch-interior read-skip, .cs hints, exact-fit 1D grid of 128-thr blocks)
// with __launch_bounds__(128, 16): forces regs <= 32 so 16 blocks/SM resident
// (64 warps = 100% theoretical occ, up from 11 blocks/46 regs = 68.75%).
// Compiler chunks the 9-channel batch into ~4/5-channel load/store groups:
// per-thread MLP drops ~2x but resident warps rise ~1.45x -> chip-level
// bytes-in-flight flat-to-better with much more issue-latency cover.
// Revert signature: LDL/STL spills / dur > 305us.

#define N_     4096
#define C_     9
#define H_     84
#define W_     84
#define PATCH_ 28
#define W4_    (W_ / 4)      // 21
#define HW4_   (H_ * W4_)    // 1764
#define TOTAL_ (N_ * HW4_)   // 7,225,344 = 56448 * 128

__global__ __launch_bounds__(128, 16)
void cutout_color_kernel(const float4* __restrict__ x,
                         const float*  __restrict__ colors,
                         const int*    __restrict__ tops,
                         const int*    __restrict__ lefts,
                         float4*       __restrict__ out)
{
    const int tid = blockIdx.x * blockDim.x + threadIdx.x;  // 0 .. TOTAL_-1, exact

    const int n = tid / HW4_;            // const-divisor -> mul/shift
    const int i = tid - n * HW4_;        // spatial vec idx 0..1763

    const int h  = i / W4_;              // const-divisor -> mul/shift
    const int w0 = (i - h * W4_) * 4;

    const int top  = tops[n];            // ~warp-uniform -> L1 broadcast
    const int left = lefts[n];

    const bool row_in = (h >= top) & (h < top + PATCH_);
    const int  lo = left, hi = left + PATCH_;

    // vec index of (n, c=0, i); channel stride HW4_. Max ~65.0M < 2^31.
    const int base = n * (C_ * HW4_) + i;

    const float* __restrict__ col = colors + n * C_;

    if (row_in & (w0 >= lo) & (w0 + 3 < hi)) {
        // whole vector inside the patch for every channel: pure writes
        #pragma unroll
        for (int c = 0; c < C_; ++c) {
            const float f = col[c];
            __stcs(&out[base + c * HW4_], make_float4(f, f, f, f));
        }
        return;
    }

    // Channel batch: under the 32-reg budget the compiler chunks this into
    // ~4/5-channel load/store groups, keeping several loads in flight each.
    float4 v[C_];
    #pragma unroll
    for (int c = 0; c < C_; ++c)
        v[c] = __ldcs(&x[base + c * HW4_]);

    if (row_in) {
        const bool m0 = (w0 + 0 >= lo) & (w0 + 0 < hi);
        const bool m1 = (w0 + 1 >= lo) & (w0 + 1 < hi);
        const bool m2 = (w0 + 2 >= lo) & (w0 + 2 < hi);
        const bool m3 = (w0 + 3 >= lo) & (w0 + 3 < hi);
        #pragma unroll
        for (int c = 0; c < C_; ++c) {
            const float f = col[c];
            if (m0) v[c].x = f;
            if (m1) v[c].y = f;
            if (m2) v[c].z = f;
            if (m3) v[c].w = f;
        }
    }

    #pragma unroll
    for (int c = 0; c < C_; ++c)
        __stcs(&out[base + c * HW4_], v[c]);
}

extern "C" void kernel_launch(void* const* d_in, const int* in_sizes, int n_in,
                              void* d_out, int out_size)
{
    const float4* x      = (const float4*)d_in[0];
    const float*  colors = (const float*) d_in[1];
    const int*    tops   = (const int*)   d_in[2];
    const int*    lefts  = (const int*)   d_in[3];
    float4*       out    = (float4*)      d_out;

    dim3 block(128);
    dim3 grid(TOTAL_ / 128);             // 56448 blocks, exact fit
    cutout_color_kernel<<<grid, block>>>(x, colors, tops, lefts, out);
}

// round 15
// speedup vs baseline: 1.3576x; 1.3576x over previous
#include <cuda_runtime.h>
#include <stdint.h>

// CutoutColor: out[n,c,h,w] = colors[n,c] if h in [top, top+28) && w in [left, left+28)
//              else x[n,c,h,w]
// x [4096, 9, 84, 84] f32, colors [4096, 9] f32, tops/lefts [4096] i32.
//
// FINAL (converged at the HBM mixed-stream ceiling, ~6.89 TB/s = 86% of spec):
//  - channel-fused: one thread = one spatial float4 across all 9 channels
//    (mask computed once, 9 front-batched independent LDG.128 -> MLP=9,
//    all 9 float4s register-resident at natural regs=46)
//  - patch-interior read-skip (fully-covered vectors never read x)
//  - .cs (evict-first) streaming hints on the bulk load/store streams
//  - flattened exact-fit 1D grid of 128-thread blocks (11 blocks/SM)
// Axes explored and closed:
//  - 8-sample/block fusion: regressed (divergence serialization, occ drop)
//  - 256-bit v8.b32: neutral (L1tex queue is per-128B-line, not per-instr)
//  - forced regs=32 / 100% occ: regressed 36% (spills; MLP > occupancy here)
//  - .cs hints: +0.5%; 128-thr blocks: +0.3%; tail removal: neutral

#define N_     4096
#define C_     9
#define H_     84
#define W_     84
#define PATCH_ 28
#define W4_    (W_ / 4)      // 21
#define HW4_   (H_ * W4_)    // 1764
#define TOTAL_ (N_ * HW4_)   // 7,225,344 = 56448 * 128

__global__ __launch_bounds__(128)
void cutout_color_kernel(const float4* __restrict__ x,
                         const float*  __restrict__ colors,
                         const int*    __restrict__ tops,
                         const int*    __restrict__ lefts,
                         float4*       __restrict__ out)
{
    const int tid = blockIdx.x * blockDim.x + threadIdx.x;  // 0 .. TOTAL_-1, exact

    const int n = tid / HW4_;            // const-divisor -> mul/shift
    const int i = tid - n * HW4_;        // spatial vec idx 0..1763

    const int h  = i / W4_;              // const-divisor -> mul/shift
    const int w0 = (i - h * W4_) * 4;

    const int top  = tops[n];            // ~warp-uniform -> L1 broadcast
    const int left = lefts[n];

    const bool row_in = (h >= top) & (h < top + PATCH_);
    const int  lo = left, hi = left + PATCH_;

    // vec index of (n, c=0, i); channel stride HW4_. Max ~65.0M < 2^31.
    const int base = n * (C_ * HW4_) + i;

    const float* __restrict__ col = colors + n * C_;

    if (row_in & (w0 >= lo) & (w0 + 3 < hi)) {
        // whole vector inside the patch for every channel: pure writes
        #pragma unroll
        for (int c = 0; c < C_; ++c) {
            const float f = col[c];
            __stcs(&out[base + c * HW4_], make_float4(f, f, f, f));
        }
        return;
    }

    // Front-batch all 9 independent streaming loads (MLP=9), then select+store.
    float4 v[C_];
    #pragma unroll
    for (int c = 0; c < C_; ++c)
        v[c] = __ldcs(&x[base + c * HW4_]);

    if (row_in) {
        const bool m0 = (w0 + 0 >= lo) & (w0 + 0 < hi);
        const bool m1 = (w0 + 1 >= lo) & (w0 + 1 < hi);
        const bool m2 = (w0 + 2 >= lo) & (w0 + 2 < hi);
        const bool m3 = (w0 + 3 >= lo) & (w0 + 3 < hi);
        #pragma unroll
        for (int c = 0; c < C_; ++c) {
            const float f = col[c];
            if (m0) v[c].x = f;
            if (m1) v[c].y = f;
            if (m2) v[c].z = f;
            if (m3) v[c].w = f;
        }
    }

    #pragma unroll
    for (int c = 0; c < C_; ++c)
        __stcs(&out[base + c * HW4_], v[c]);
}

extern "C" void kernel_launch(void* const* d_in, const int* in_sizes, int n_in,
                              void* d_out, int out_size)
{
    const float4* x      = (const float4*)d_in[0];
    const float*  colors = (const float*) d_in[1];
    const int*    tops   = (const int*)   d_in[2];
    const int*    lefts  = (const int*)   d_in[3];
    float4*       out    = (float4*)      d_out;

    dim3 block(128);
    dim3 grid(TOTAL_ / 128);             // 56448 blocks, exact fit
    cutout_color_kernel<<<grid, block>>>(x, colors, tops, lefts, out);
}

// round 16
// speedup vs baseline: 1.3643x; 1.0049x over previous
#include <cuda_runtime.h>
#include <stdint.h>

// CutoutColor: out[n,c,h,w] = colors[n,c] if h in [top, top+28) && w in [left, left+28)
//              else x[n,c,h,w]
// x [4096, 9, 84, 84] f32, colors [4096, 9] f32, tops/lefts [4096] i32.
//
// FINAL — converged at the HBM mixed-stream roofline.
// Measured: 2.04 GB moved (theoretical min ~2.00 GB) at 6.84-6.89 TB/s
// (86% of 8 TB/s spec, = pure-copy ceiling on this part). dur 299.5-300.6us
// across 5 reruns (noise band).
//
// Structure:
//  - channel-fused: one thread = one spatial float4 across all 9 channels
//    (mask computed once; 9 front-batched independent LDG.128 -> MLP=9;
//    all 9 float4s register-resident at natural regs=46)
//  - patch-interior read-skip (fully-covered vectors never read x)
//  - .cs (evict-first) streaming hints on bulk load/store (+0.5%)
//  - flattened exact-fit 1D grid, 128-thread blocks (11 blocks/SM, +0.3%)
// Axes explored and closed:
//  - 8-sample/block fusion: regressed (divergence serialization, occ drop)
//  - 256-bit v8.b32: neutral (L1tex queue is per-128B-line, not per-instr)
//  - forced regs=32 / 100% occ: regressed 36% (spills; MLP > occupancy here)
//  - memcpy+paint two-pass: rejected on traffic (2.2 GB > 2.04 GB)

#define N_     4096
#define C_     9
#define H_     84
#define W_     84
#define PATCH_ 28
#define W4_    (W_ / 4)      // 21
#define HW4_   (H_ * W4_)    // 1764
#define TOTAL_ (N_ * HW4_)   // 7,225,344 = 56448 * 128

__global__ __launch_bounds__(128)
void cutout_color_kernel(const float4* __restrict__ x,
                         const float*  __restrict__ colors,
                         const int*    __restrict__ tops,
                         const int*    __restrict__ lefts,
                         float4*       __restrict__ out)
{
    const int tid = blockIdx.x * blockDim.x + threadIdx.x;  // 0 .. TOTAL_-1, exact

    const int n = tid / HW4_;            // const-divisor -> mul/shift
    const int i = tid - n * HW4_;        // spatial vec idx 0..1763

    const int h  = i / W4_;              // const-divisor -> mul/shift
    const int w0 = (i - h * W4_) * 4;

    const int top  = tops[n];            // ~warp-uniform -> L1 broadcast
    const int left = lefts[n];

    const bool row_in = (h >= top) & (h < top + PATCH_);
    const int  lo = left, hi = left + PATCH_;

    // vec index of (n, c=0, i); channel stride HW4_. Max ~65.0M < 2^31.
    const int base = n * (C_ * HW4_) + i;

    const float* __restrict__ col = colors + n * C_;

    if (row_in & (w0 >= lo) & (w0 + 3 < hi)) {
        // whole vector inside the patch for every channel: pure writes
        #pragma unroll
        for (int c = 0; c < C_; ++c) {
            const float f = col[c];
            __stcs(&out[base + c * HW4_], make_float4(f, f, f, f));
        }
        return;
    }

    // Front-batch all 9 independent streaming loads (MLP=9), then select+store.
    float4 v[C_];
    #pragma unroll
    for (int c = 0; c < C_; ++c)
        v[c] = __ldcs(&x[base + c * HW4_]);

    if (row_in) {
        const bool m0 = (w0 + 0 >= lo) & (w0 + 0 < hi);
        const bool m1 = (w0 + 1 >= lo) & (w0 + 1 < hi);
        const bool m2 = (w0 + 2 >= lo) & (w0 + 2 < hi);
        const bool m3 = (w0 + 3 >= lo) & (w0 + 3 < hi);
        #pragma unroll
        for (int c = 0; c < C_; ++c) {
            const float f = col[c];
            if (m0) v[c].x = f;
            if (m1) v[c].y = f;
            if (m2) v[c].z = f;
            if (m3) v[c].w = f;
        }
    }

    #pragma unroll
    for (int c = 0; c < C_; ++c)
        __stcs(&out[base + c * HW4_], v[c]);
}

extern "C" void kernel_launch(void* const* d_in, const int* in_sizes, int n_in,
                              void* d_out, int out_size)
{
    const float4* x      = (const float4*)d_in[0];
    const float*  colors = (const float*) d_in[1];
    const int*    tops   = (const int*)   d_in[2];
    const int*    lefts  = (const int*)   d_in[3];
    float4*       out    = (float4*)      d_out;

    dim3 block(128);
    dim3 grid(TOTAL_ / 128);             // 56448 blocks, exact fit
    cutout_color_kernel<<<grid, block>>>(x, colors, tops, lefts, out);
}